// round 8
// baseline (speedup 1.0000x reference)
#include <cuda_runtime.h>
#include <cstdint>
#include <math.h>

#define BATCH 4
#define SEQ   4096
#define DIM   512
#define ROWS  (BATCH*SEQ)   // 16384
#define NCHUNK 32
#define CHUNK  128          // SEQ / NCHUNK
#define CLSZ   8            // cluster size for chain

// ---- scratch (no cudaMalloc allowed) ----
__device__ float g_R[ROWS*DIM];
__device__ float g_G[ROWS*DIM];
__device__ float g_C[ROWS*DIM];
__device__ float g_S[ROWS*DIM];
__device__ float g_cf[BATCH*NCHUNK*DIM];
__device__ float g_cp[BATCH*NCHUNK*DIM];

// ---------------- helpers ----------------
__device__ __forceinline__ uint32_t smem_u32(const void* p) {
    return (uint32_t)__cvta_generic_to_shared(p);
}
__device__ __forceinline__ void fma2(unsigned long long& d, unsigned long long a, unsigned long long b) {
    asm("fma.rn.f32x2 %0, %1, %2, %0;" : "+l"(d) : "l"(a), "l"(b));
}
__device__ __forceinline__ unsigned long long dupf(float a) {
    unsigned long long r;
    asm("mov.b64 %0, {%1, %1};" : "=l"(r) : "f"(a));
    return r;
}
__device__ __forceinline__ void unpack2(unsigned long long v, float& lo, float& hi) {
    asm("mov.b64 {%0, %1}, %2;" : "=f"(lo), "=f"(hi) : "l"(v));
}
__device__ __forceinline__ void mbar_init(uint32_t addr, uint32_t cnt) {
    asm volatile("mbarrier.init.shared.b64 [%0], %1;" :: "r"(addr), "r"(cnt) : "memory");
}
__device__ __forceinline__ void mbar_expect_tx(uint32_t addr, uint32_t bytes) {
    asm volatile("mbarrier.arrive.expect_tx.shared.b64 _, [%0], %1;" :: "r"(addr), "r"(bytes) : "memory");
}
__device__ __forceinline__ void st_async_u32(uint32_t raddr, uint32_t val, uint32_t rmbar) {
    asm volatile("st.async.weak.shared::cluster.mbarrier::complete_tx::bytes.b32 [%0], %1, [%2];"
                 :: "r"(raddr), "r"(val), "r"(rmbar) : "memory");
}
__device__ __forceinline__ void mbar_wait(uint32_t addr, uint32_t parity) {
    uint32_t done;
    asm volatile("{\n\t.reg .pred P;\n\t"
        "mbarrier.try_wait.parity.acquire.cta.shared::cta.b64 P, [%1], %2, 0x989680;\n\t"
        "selp.b32 %0, 1, 0, P;\n\t}"
        : "=r"(done) : "r"(addr), "r"(parity) : "memory");
    while (!done) {
        asm volatile("{\n\t.reg .pred P;\n\t"
            "mbarrier.try_wait.parity.acquire.cta.shared::cta.b64 P, [%1], %2, 0x989680;\n\t"
            "selp.b32 %0, 1, 0, P;\n\t}"
            : "=r"(done) : "r"(addr), "r"(parity) : "memory");
    }
}
#define CLUSTER_SYNC() do { \
    asm volatile("barrier.cluster.arrive.aligned;" ::: "memory"); \
    asm volatile("barrier.cluster.wait.aligned;"   ::: "memory"); } while (0)

// ============================================================
// Chunked linear scan for r
// ============================================================
__global__ void scan_local(const float* __restrict__ k, const float* __restrict__ v,
                           const float* __restrict__ decay, int store)
{
    int g = blockIdx.x*blockDim.x + threadIdx.x;
    int d = g % DIM;
    int c = (g / DIM) % NCHUNK;
    int b = g / (DIM*NCHUNK);
    float dec = decay[d >> 6];
    float r = store ? g_cp[g] : 0.0f;
    size_t base = ((size_t)b*SEQ + (size_t)c*CHUNK)*DIM + d;
    #pragma unroll 4
    for (int u = 0; u < CHUNK; u++) {
        size_t off = base + (size_t)u*DIM;
        r = fmaf(dec, r, k[off]*v[off]);
        if (store) g_R[off] = r;
    }
    if (!store) g_cf[g] = r;
}

__global__ void scan_prefix(const float* __restrict__ decay)
{
    int g = blockIdx.x*blockDim.x + threadIdx.x;
    int d = g % DIM;
    int b = g / DIM;
    float dec = decay[d >> 6];
    float dp = powf(dec, (float)CHUNK);
    float p = 0.0f;
    for (int c = 0; c < NCHUNK; c++) {
        int idx = (b*NCHUNK + c)*DIM + d;
        g_cp[idx] = p;
        p = g_cf[idx] + dp*p;
    }
}

// ============================================================
// GEMM: Y[M,512] = act(X[M,512] @ W[512,512]^T + bias), f32x2 inner
// ============================================================
__global__ __launch_bounds__(256)
void gemm_kernel(const float* __restrict__ X, const float* __restrict__ W,
                 const float* __restrict__ bias, float* __restrict__ Y, int act)
{
    __shared__ __align__(16) float Xs[16][132];
    __shared__ __align__(16) float Ws[16][132];
    const int K = DIM;
    int tid  = threadIdx.x;
    int m0   = blockIdx.y * 128;
    int n0   = blockIdx.x * 128;
    int rowc = (tid >> 4) << 3;
    int colc = (tid & 15) << 3;

    unsigned long long acc2[8][4];
    #pragma unroll
    for (int i = 0; i < 8; i++)
        #pragma unroll
        for (int j = 0; j < 4; j++) acc2[i][j] = 0ull;

    for (int kt = 0; kt < K; kt += 16) {
        #pragma unroll
        for (int l = 0; l < 2; l++) {
            int idx = tid + l*256;
            int row = idx >> 2;
            int fc  = (idx & 3) << 2;
            float4 xv = *(const float4*)(X + (size_t)(m0+row)*K + kt + fc);
            Xs[fc+0][row]=xv.x; Xs[fc+1][row]=xv.y; Xs[fc+2][row]=xv.z; Xs[fc+3][row]=xv.w;
            float4 wv = *(const float4*)(W + (size_t)(n0+row)*K + kt + fc);
            Ws[fc+0][row]=wv.x; Ws[fc+1][row]=wv.y; Ws[fc+2][row]=wv.z; Ws[fc+3][row]=wv.w;
        }
        __syncthreads();
        #pragma unroll
        for (int kk = 0; kk < 16; kk++) {
            float ar[8];
            *(float4*)(ar  ) = *(const float4*)&Xs[kk][rowc];
            *(float4*)(ar+4) = *(const float4*)&Xs[kk][rowc+4];
            ulonglong2 blo = *(const ulonglong2*)&Ws[kk][colc];
            ulonglong2 bhi = *(const ulonglong2*)&Ws[kk][colc+4];
            #pragma unroll
            for (int i = 0; i < 8; i++) {
                unsigned long long ad = dupf(ar[i]);
                fma2(acc2[i][0], ad, blo.x);
                fma2(acc2[i][1], ad, blo.y);
                fma2(acc2[i][2], ad, bhi.x);
                fma2(acc2[i][3], ad, bhi.y);
            }
        }
        __syncthreads();
    }

    #pragma unroll
    for (int i = 0; i < 8; i++) {
        float out[8];
        #pragma unroll
        for (int jp = 0; jp < 4; jp++) unpack2(acc2[i][jp], out[2*jp], out[2*jp+1]);
        #pragma unroll
        for (int j = 0; j < 8; j++) {
            float val = out[j] + (bias ? bias[n0+colc+j] : 0.0f);
            if (act == 1) val = 1.0f/(1.0f + expf(-val));
            Y[(size_t)(m0+rowc+i)*DIM + n0+colc+j] = val;
        }
    }
}

// ============================================================
// Sequential chain: 4 batches x 8-CTA clusters, 256 threads/CTA.
// WARP-AUTONOMOUS steps: warp w owns rows [w*8, w*8+8) of its slice;
// lane = 4*rowInWarp + kpart, kpart covers interleaved k (float4
// groups k=16u+4*kpart) so warp LDS stays near 1 wavefront/instr.
// Per step: wait -> MAC -> 2x shfl -> tanh -> st.async. NO __syncthreads.
// Reuse safety: peer overwrites bl[p] only after its wait(bar[1-p])
// passes, which needs OUR stores, which depend on OUR bl[p] reads.
// ============================================================
__global__ void __launch_bounds__(256, 1) __cluster_dims__(CLSZ, 1, 1)
chain_kernel(const float* __restrict__ q, const float* __restrict__ A,
             const float* __restrict__ G, const float* __restrict__ C,
             float* __restrict__ Sout)
{
    __shared__ __align__(16) float bl[2][DIM];            // double-buffered blended
    __shared__ __align__(8)  unsigned long long mbar[2];  // one barrier per buffer

    int rank = blockIdx.x & (CLSZ-1);
    int b    = blockIdx.x / CLSZ;
    int tid  = threadIdx.x;
    int w    = tid >> 5;
    int lane = tid & 31;
    int rw   = lane >> 2;         // row within warp's 8 (0..7)
    int kp   = lane & 3;          // k-partition (interleaved)
    int jg   = rank*64 + w*8 + rw;  // global output row (0..511)
    bool wr  = (kp == 0);         // writer lane

    uint32_t bl_a = smem_u32(&bl[0][0]);
    uint32_t mb_a = smem_u32(&mbar[0]);
    uint32_t dmb  = mb_a - bl_a;

    if (tid == 0) { mbar_init(mb_a, 1); mbar_init(mb_a + 8, 1); }

    // remote bl base of every cluster CTA
    uint32_t rb[CLSZ];
    #pragma unroll
    for (int r = 0; r < CLSZ; r++)
        asm("mapa.shared::cluster.u32 %0, %1, %2;" : "=r"(rb[r]) : "r"(bl_a), "r"(r));

    // A slice: row jg, float4 groups k = 16u + 4*kp, u = 0..31 (128 floats)
    unsigned long long a2[64];
    #pragma unroll
    for (int u = 0; u < 32; u++) {
        ulonglong2 av = *(const ulonglong2*)(A + (size_t)jg*DIM + 16*u + 4*kp);
        a2[2*u] = av.x; a2[2*u+1] = av.y;
    }

    const float* qb = q    + (size_t)b*SEQ*DIM;
    const float* Gb = G    + (size_t)b*SEQ*DIM;
    const float* Cb = C    + (size_t)b*SEQ*DIM;
    float*       Sb = Sout + (size_t)b*SEQ*DIM;

    // arm buffer 0, then cluster-wide publish of initial blended
    if (tid == 0) mbar_expect_tx(mb_a, 2048);
    CLUSTER_SYNC();   // barriers initialized + armed before any st.async

    float cc = 0.f, cg = 0.f, cq = 0.f;
    if (wr) {
        float g0 = Gb[jg], q0 = qb[jg];
        uint32_t bits = __float_as_uint((1.0f - g0) * q0);   // state_0 = 0
        #pragma unroll
        for (int r = 0; r < CLSZ; r++)
            st_async_u32(rb[r] + (uint32_t)jg*4u, bits, rb[r] + dmb);
        cc = Cb[jg]; cg = Gb[DIM + jg]; cq = qb[DIM + jg];
    }

    for (int t = 0; t < SEQ; t++) {
        int p = t & 1;
        uint32_t ph = (t >> 1) & 1;

        // prefetch next operands + arm next buffer's barrier BEFORE waiting
        float nc = 0.f, ng = 0.f, nq = 0.f;
        if (wr) {
            if (t+1 < SEQ) nc = Cb[(size_t)(t+1)*DIM + jg];
            if (t+2 < SEQ) { ng = Gb[(size_t)(t+2)*DIM + jg]; nq = qb[(size_t)(t+2)*DIM + jg]; }
        }
        if (tid == 0 && t+1 < SEQ) mbar_expect_tx(mb_a + (uint32_t)(1-p)*8u, 2048);

        mbar_wait(mb_a + (uint32_t)p*8u, ph);

        // 128 MACs/lane over interleaved k (warp LDS ~1 wavefront/instr)
        unsigned long long acc0 = 0ull, acc1 = 0ull;
        const float* blp = bl[p];
        #pragma unroll
        for (int u = 0; u < 32; u++) {
            ulonglong2 bv = *(const ulonglong2*)(blp + 16*u + 4*kp);
            fma2(acc0, a2[2*u],   bv.x);
            fma2(acc1, a2[2*u+1], bv.y);
        }
        float x0, x1, y0, y1;
        unpack2(acc0, x0, x1);
        unpack2(acc1, y0, y1);
        float acc = (x0 + x1) + (y0 + y1);
        // reduce over 4 k-partitions (contiguous lanes)
        acc += __shfl_xor_sync(0xffffffffu, acc, 1);
        acc += __shfl_xor_sync(0xffffffffu, acc, 2);

        if (wr) {
            float s = tanhf(acc + cc);
            Sb[(size_t)t*DIM + jg] = s;
            if (t+1 < SEQ) {
                uint32_t bits = __float_as_uint(fmaf(cg, s - cq, cq)); // g*s+(1-g)*q
                uint32_t boff = (uint32_t)(1-p)*2048u + (uint32_t)jg*4u;
                uint32_t moff = dmb + (uint32_t)(1-p)*8u;
                #pragma unroll
                for (int r = 0; r < CLSZ; r++)
                    st_async_u32(rb[r] + boff, bits, rb[r] + moff);
            }
            cc = nc; cg = ng; cq = nq;
        }
    }
}

// ============================================================
// launch
// ============================================================
extern "C" void kernel_launch(void* const* d_in, const int* in_sizes, int n_in,
                              void* d_out, int out_size)
{
    const float* q     = (const float*)d_in[0];
    const float* k     = (const float*)d_in[1];
    const float* v     = (const float*)d_in[2];
    const float* A     = (const float*)d_in[3];
    const float* Bm    = (const float*)d_in[4];
    const float* gw    = (const float*)d_in[5];
    const float* gb    = (const float*)d_in[6];
    const float* ow    = (const float*)d_in[7];
    const float* ob    = (const float*)d_in[8];
    const float* decay = (const float*)d_in[9];
    float* out = (float*)d_out;

    float *R, *G, *C, *S;
    cudaGetSymbolAddress((void**)&R, g_R);
    cudaGetSymbolAddress((void**)&G, g_G);
    cudaGetSymbolAddress((void**)&C, g_C);
    cudaGetSymbolAddress((void**)&S, g_S);

    // 1) chunked linear scan for r
    scan_local <<<BATCH*NCHUNK*DIM/256, 256>>>(k, v, decay, 0);
    scan_prefix<<<BATCH*DIM/256,        256>>>(decay);
    scan_local <<<BATCH*NCHUNK*DIM/256, 256>>>(k, v, decay, 1);

    dim3 ggrid(DIM/128, ROWS/128);
    // 2) gates (sigmoid epilogue)
    gemm_kernel<<<ggrid, 256>>>(q, gw, gb, G, 1);
    // 3) C = R @ Bm^T
    gemm_kernel<<<ggrid, 256>>>(R, Bm, nullptr, C, 0);
    // 4) sequential recurrent chain (4 clusters of 8 CTAs)
    chain_kernel<<<BATCH*CLSZ, 256>>>(q, A, G, C, S);
    // 5) out projection
    gemm_kernel<<<ggrid, 256>>>(S, ow, ob, out, 0);
}

// round 9
// speedup vs baseline: 1.0236x; 1.0236x over previous
#include <cuda_runtime.h>
#include <cstdint>
#include <math.h>

#define BATCH 4
#define SEQ   4096
#define DIM   512
#define ROWS  (BATCH*SEQ)   // 16384
#define NCHUNK 32
#define CHUNK  128          // SEQ / NCHUNK
#define CLSZ   8            // cluster size
#define NCHAIN 32           // chain CTAs (4 clusters)
#define NWORK  96           // worker CTAs (12 clusters)
#define NCH    (ROWS/128)   // 128 row-chunks of 128 rows

// ---- scratch (no cudaMalloc allowed) ----
__device__ float g_R[ROWS*DIM];
__device__ float g_G[ROWS*DIM];
__device__ float g_C[ROWS*DIM];
__device__ float g_S[ROWS*DIM];
__device__ float g_cf[BATCH*NCHUNK*DIM];
__device__ float g_cp[BATCH*NCHUNK*DIM];
__device__ unsigned g_flagG[NCH];   // ==4 when all 4 n-tiles of chunk done
__device__ unsigned g_flagC[NCH];
__device__ unsigned g_flagS[NCH];   // ==8 when all 8 cluster CTAs past chunk

// ---------------- helpers ----------------
__device__ __forceinline__ uint32_t smem_u32(const void* p) {
    return (uint32_t)__cvta_generic_to_shared(p);
}
__device__ __forceinline__ void fma2(unsigned long long& d, unsigned long long a, unsigned long long b) {
    asm("fma.rn.f32x2 %0, %1, %2, %0;" : "+l"(d) : "l"(a), "l"(b));
}
__device__ __forceinline__ unsigned long long dupf(float a) {
    unsigned long long r;
    asm("mov.b64 %0, {%1, %1};" : "=l"(r) : "f"(a));
    return r;
}
__device__ __forceinline__ void unpack2(unsigned long long v, float& lo, float& hi) {
    asm("mov.b64 {%0, %1}, %2;" : "=f"(lo), "=f"(hi) : "l"(v));
}
__device__ __forceinline__ void mbar_init(uint32_t addr, uint32_t cnt) {
    asm volatile("mbarrier.init.shared.b64 [%0], %1;" :: "r"(addr), "r"(cnt) : "memory");
}
__device__ __forceinline__ void mbar_expect_tx(uint32_t addr, uint32_t bytes) {
    asm volatile("mbarrier.arrive.expect_tx.shared.b64 _, [%0], %1;" :: "r"(addr), "r"(bytes) : "memory");
}
__device__ __forceinline__ void st_async_u32(uint32_t raddr, uint32_t val, uint32_t rmbar) {
    asm volatile("st.async.weak.shared::cluster.mbarrier::complete_tx::bytes.b32 [%0], %1, [%2];"
                 :: "r"(raddr), "r"(val), "r"(rmbar) : "memory");
}
__device__ __forceinline__ void mbar_wait(uint32_t addr, uint32_t parity) {
    uint32_t done;
    asm volatile("{\n\t.reg .pred P;\n\t"
        "mbarrier.try_wait.parity.acquire.cta.shared::cta.b64 P, [%1], %2, 0x989680;\n\t"
        "selp.b32 %0, 1, 0, P;\n\t}"
        : "=r"(done) : "r"(addr), "r"(parity) : "memory");
    while (!done) {
        asm volatile("{\n\t.reg .pred P;\n\t"
            "mbarrier.try_wait.parity.acquire.cta.shared::cta.b64 P, [%1], %2, 0x989680;\n\t"
            "selp.b32 %0, 1, 0, P;\n\t}"
            : "=r"(done) : "r"(addr), "r"(parity) : "memory");
    }
}
#define CLUSTER_SYNC() do { \
    asm volatile("barrier.cluster.arrive.aligned;" ::: "memory"); \
    asm volatile("barrier.cluster.wait.aligned;"   ::: "memory"); } while (0)

// volatile-spin on a flag, then acquire fence
__device__ __forceinline__ void spin_flag(volatile unsigned* f, unsigned target) {
    while (*f < target) __nanosleep(64);
    __threadfence();
}

// ============================================================
// zero the cross-CTA flags (runs each replay, before mega kernel)
// ============================================================
__global__ void zero_flags()
{
    int i = threadIdx.x;
    if (i < NCH) { g_flagG[i] = 0; g_flagC[i] = 0; g_flagS[i] = 0; }
}

// ============================================================
// Chunked linear scan for r
// ============================================================
__global__ void scan_local(const float* __restrict__ k, const float* __restrict__ v,
                           const float* __restrict__ decay, int store)
{
    int g = blockIdx.x*blockDim.x + threadIdx.x;
    int d = g % DIM;
    int c = (g / DIM) % NCHUNK;
    int b = g / (DIM*NCHUNK);
    float dec = decay[d >> 6];
    float r = store ? g_cp[g] : 0.0f;
    size_t base = ((size_t)b*SEQ + (size_t)c*CHUNK)*DIM + d;
    #pragma unroll 4
    for (int u = 0; u < CHUNK; u++) {
        size_t off = base + (size_t)u*DIM;
        r = fmaf(dec, r, k[off]*v[off]);
        if (store) g_R[off] = r;
    }
    if (!store) g_cf[g] = r;
}

__global__ void scan_prefix(const float* __restrict__ decay)
{
    int g = blockIdx.x*blockDim.x + threadIdx.x;
    int d = g % DIM;
    int b = g / DIM;
    float dec = decay[d >> 6];
    float dp = powf(dec, (float)CHUNK);
    float p = 0.0f;
    for (int c = 0; c < NCHUNK; c++) {
        int idx = (b*NCHUNK + c)*DIM + d;
        g_cp[idx] = p;
        p = g_cf[idx] + dp*p;
    }
}

// ============================================================
// device GEMM tile: Y[m0:+128, n0:+128] = act(X@W^T + bias)
// 256 threads, f32x2 inner. Same scheme as the standalone gemm.
// ============================================================
struct WorkSmem { float Xs[16][132]; float Ws[16][132]; };

__device__ void gemm_tile(const float* __restrict__ X, const float* __restrict__ W,
                          const float* __restrict__ bias, float* __restrict__ Y,
                          int act, int m0, int n0, WorkSmem* sm)
{
    const int K = DIM;
    int tid  = threadIdx.x;
    int rowc = (tid >> 4) << 3;
    int colc = (tid & 15) << 3;

    unsigned long long acc2[8][4];
    #pragma unroll
    for (int i = 0; i < 8; i++)
        #pragma unroll
        for (int j = 0; j < 4; j++) acc2[i][j] = 0ull;

    for (int kt = 0; kt < K; kt += 16) {
        #pragma unroll
        for (int l = 0; l < 2; l++) {
            int idx = tid + l*256;
            int row = idx >> 2;
            int fc  = (idx & 3) << 2;
            float4 xv = *(const float4*)(X + (size_t)(m0+row)*K + kt + fc);
            sm->Xs[fc+0][row]=xv.x; sm->Xs[fc+1][row]=xv.y; sm->Xs[fc+2][row]=xv.z; sm->Xs[fc+3][row]=xv.w;
            float4 wv = *(const float4*)(W + (size_t)(n0+row)*K + kt + fc);
            sm->Ws[fc+0][row]=wv.x; sm->Ws[fc+1][row]=wv.y; sm->Ws[fc+2][row]=wv.z; sm->Ws[fc+3][row]=wv.w;
        }
        __syncthreads();
        #pragma unroll
        for (int kk = 0; kk < 16; kk++) {
            float ar[8];
            *(float4*)(ar  ) = *(const float4*)&sm->Xs[kk][rowc];
            *(float4*)(ar+4) = *(const float4*)&sm->Xs[kk][rowc+4];
            ulonglong2 blo = *(const ulonglong2*)&sm->Ws[kk][colc];
            ulonglong2 bhi = *(const ulonglong2*)&sm->Ws[kk][colc+4];
            #pragma unroll
            for (int i = 0; i < 8; i++) {
                unsigned long long ad = dupf(ar[i]);
                fma2(acc2[i][0], ad, blo.x);
                fma2(acc2[i][1], ad, blo.y);
                fma2(acc2[i][2], ad, bhi.x);
                fma2(acc2[i][3], ad, bhi.y);
            }
        }
        __syncthreads();
    }

    #pragma unroll
    for (int i = 0; i < 8; i++) {
        float out[8];
        #pragma unroll
        for (int jp = 0; jp < 4; jp++) unpack2(acc2[i][jp], out[2*jp], out[2*jp+1]);
        #pragma unroll
        for (int j = 0; j < 8; j++) {
            float val = out[j] + (bias ? bias[n0+colc+j] : 0.0f);
            if (act == 1) val = 1.0f/(1.0f + expf(-val));
            Y[(size_t)(m0+rowc+i)*DIM + n0+colc+j] = val;
        }
    }
}

// ============================================================
// MEGA KERNEL: 128 CTAs (16 clusters of 8), 256 threads.
//  - CTAs 0..31  : recurrent chain (R6 structure, 3980us version)
//  - CTAs 32..127: GEMM workers (G, C in chunk order; out after S chunks)
// ============================================================
__global__ void __launch_bounds__(256, 1) __cluster_dims__(CLSZ, 1, 1)
mega_kernel(const float* __restrict__ q, const float* __restrict__ A,
            const float* __restrict__ gw, const float* __restrict__ gb,
            const float* __restrict__ Bm, const float* __restrict__ ow,
            const float* __restrict__ ob, float* __restrict__ out)
{
    __shared__ __align__(16) float bl[2][DIM];
    __shared__ __align__(16) float part[64][4];
    __shared__ __align__(8)  unsigned long long mbar[4];  // [buf][half]
    __shared__ WorkSmem wsm;

    const float* G = g_G;
    const float* C = g_C;
    int bid = blockIdx.x;
    int tid = threadIdx.x;

    if (bid >= NCHAIN) {
        // ===================== WORKER PATH =====================
        int wk = bid - NCHAIN;
        // pre-tiles (G and C), chunk-major: i -> c=i/32, r=i%32, b=r/8,
        // kind=(r&4)?C:G, n=r&3. m-chunk = b*32+c.
        for (int i = wk; i < 1024; i += NWORK) {
            int c = i >> 5, r = i & 31;
            int b = r >> 3, kind = (r >> 2) & 1, n = r & 3;
            int mc = b*32 + c;
            if (kind == 0) {
                gemm_tile(q, gw, gb, g_G, 1, mc*128, n*128, &wsm);
                __syncthreads();
                __threadfence();
                if (tid == 0) atomicAdd(&g_flagG[mc], 1u);
            } else {
                gemm_tile(g_R, Bm, nullptr, g_C, 0, mc*128, n*128, &wsm);
                __syncthreads();
                __threadfence();
                if (tid == 0) atomicAdd(&g_flagC[mc], 1u);
            }
        }
        // out tiles, chunk-major: j -> c=j/16, r=j%16, b=r/4, n=r&3
        for (int j = wk; j < 512; j += NWORK) {
            int c = j >> 4, r = j & 15;
            int b = r >> 2, n = r & 3;
            int mc = b*32 + c;
            if (tid == 0) spin_flag(&g_flagS[mc], CLSZ);
            __syncthreads();
            gemm_tile(g_S, ow, ob, out, 0, mc*128, n*128, &wsm);
        }
        return;
    }

    // ===================== CHAIN PATH (R6 3980us structure) =====================
    int rank = bid & (CLSZ-1);
    int b    = bid / CLSZ;
    int w    = tid >> 5;
    int lane = tid & 31;
    int qw   = w >> 1;            // k-quarter (0..3)
    int rh   = w & 1;             // row-half
    int jl   = rh*32 + lane;      // row within slice
    int jg   = rank*64 + jl;
    int kbase= qw*128;
    int hw   = qw >> 1;           // half this warp consumes
    int myh  = rank >> 2;         // half this CTA produces

    uint32_t bl_a = smem_u32(&bl[0][0]);
    uint32_t mb_a = smem_u32(&mbar[0]);
    uint32_t dmb  = mb_a - bl_a;

    if (tid == 0) {
        mbar_init(mb_a,      1);
        mbar_init(mb_a + 8,  1);
        mbar_init(mb_a + 16, 1);
        mbar_init(mb_a + 24, 1);
    }

    uint32_t rb[CLSZ];
    #pragma unroll
    for (int r = 0; r < CLSZ; r++)
        asm("mapa.shared::cluster.u32 %0, %1, %2;" : "=r"(rb[r]) : "r"(bl_a), "r"(r));

    unsigned long long a2[64];
    #pragma unroll
    for (int u = 0; u < 32; u++) {
        ulonglong2 av = *(const ulonglong2*)(A + (size_t)jg*DIM + kbase + 4*u);
        a2[2*u] = av.x; a2[2*u+1] = av.y;
    }

    const float* qb = q   + (size_t)b*SEQ*DIM;
    const float* Gb = G   + (size_t)b*SEQ*DIM;
    const float* Cb = C   + (size_t)b*SEQ*DIM;
    float*       Sb = g_S + (size_t)b*SEQ*DIM;

    if (tid == 0) {                   // arm both halves of buffer 0
        mbar_expect_tx(mb_a,     1024);
        mbar_expect_tx(mb_a + 8, 1024);
    }
    CLUSTER_SYNC();

    // wait for G/C chunks 0 and 1 of this batch before any reads
    if (tid == 0) {
        spin_flag(&g_flagG[b*32],     4);
        spin_flag(&g_flagC[b*32],     4);
        spin_flag(&g_flagG[b*32 + 1], 4);
        spin_flag(&g_flagC[b*32 + 1], 4);
    }
    __syncthreads();

    int je = rank*64 + tid;           // epilogue row (tid < 64)
    float cc = 0.f, cg = 0.f, cq = 0.f;
    if (tid < 64) {
        float g0 = Gb[je], q0 = qb[je];
        uint32_t bits = __float_as_uint((1.0f - g0) * q0);   // state_0 = 0
        uint32_t moff = dmb + (uint32_t)myh*8u;
        #pragma unroll
        for (int r = 0; r < CLSZ; r++)
            st_async_u32(rb[r] + (uint32_t)je*4u, bits, rb[r] + moff);
        cc = Cb[je]; cg = Gb[DIM + je]; cq = qb[DIM + je];
    }

    for (int t = 0; t < SEQ; t++) {
        int p = t & 1;
        uint32_t ph = (t >> 1) & 1;

        // chunk-boundary: ensure next G/C chunk is ready before prefetching it
        if ((t & 127) == 0 && t != 0) {
            int ch = (t >> 7) + 1;
            if (ch < 32) {
                if (tid == 0) {
                    spin_flag(&g_flagG[b*32 + ch], 4);
                    spin_flag(&g_flagC[b*32 + ch], 4);
                }
                __syncthreads();
            }
        }

        float nc = 0.f, ng = 0.f, nq = 0.f;
        if (tid < 64) {
            if (t+1 < SEQ) nc = Cb[(size_t)(t+1)*DIM + je];
            if (t+2 < SEQ) { ng = Gb[(size_t)(t+2)*DIM + je]; nq = qb[(size_t)(t+2)*DIM + je]; }
        }
        if (tid == 0 && t+1 < SEQ) {
            mbar_expect_tx(mb_a + (uint32_t)(1-p)*16u,      1024);
            mbar_expect_tx(mb_a + (uint32_t)(1-p)*16u + 8u, 1024);
        }

        mbar_wait(mb_a + (uint32_t)p*16u + (uint32_t)hw*8u, ph);

        unsigned long long acc0 = 0ull, acc1 = 0ull;
        const float* blp = bl[p] + kbase;
        #pragma unroll
        for (int u = 0; u < 32; u++) {
            ulonglong2 bv = *(const ulonglong2*)(blp + 4*u);
            fma2(acc0, a2[2*u],   bv.x);
            fma2(acc1, a2[2*u+1], bv.y);
        }
        float x0, x1, y0, y1;
        unpack2(acc0, x0, x1);
        unpack2(acc1, y0, y1);
        part[jl][qw] = (x0 + x1) + (y0 + y1);

        __syncthreads();

        // publish S-chunk completion (stores of steps <= t-1 are ordered
        // before this sync for all threads)
        if ((t & 127) == 0 && t != 0 && tid == 0) {
            __threadfence();
            atomicAdd(&g_flagS[b*32 + (t >> 7) - 1], 1u);
        }

        if (tid < 64) {
            float4 pr = *(const float4*)&part[tid][0];
            float acc = (pr.x + pr.y) + (pr.z + pr.w);
            float s = tanhf(acc + cc);
            Sb[(size_t)t*DIM + je] = s;
            if (t+1 < SEQ) {
                uint32_t bits = __float_as_uint(fmaf(cg, s - cq, cq));
                uint32_t boff = (uint32_t)(1-p)*2048u + (uint32_t)je*4u;
                uint32_t moff = dmb + (uint32_t)(1-p)*16u + (uint32_t)myh*8u;
                #pragma unroll
                for (int r = 0; r < CLSZ; r++)
                    st_async_u32(rb[r] + boff, bits, rb[r] + moff);
            }
            cc = nc; cg = ng; cq = nq;
        }
    }

    // final chunk flag
    __syncthreads();
    if (tid == 0) {
        __threadfence();
        atomicAdd(&g_flagS[b*32 + 31], 1u);
    }
}

// ============================================================
// launch
// ============================================================
extern "C" void kernel_launch(void* const* d_in, const int* in_sizes, int n_in,
                              void* d_out, int out_size)
{
    const float* q     = (const float*)d_in[0];
    const float* k     = (const float*)d_in[1];
    const float* v     = (const float*)d_in[2];
    const float* A     = (const float*)d_in[3];
    const float* Bm    = (const float*)d_in[4];
    const float* gw    = (const float*)d_in[5];
    const float* gb    = (const float*)d_in[6];
    const float* ow    = (const float*)d_in[7];
    const float* ob    = (const float*)d_in[8];
    const float* decay = (const float*)d_in[9];
    float* out = (float*)d_out;

    // flags must be zero at mega-kernel start on every replay
    zero_flags<<<1, 128>>>();

    // chunked linear scan for r (feeds C tiles computed by workers)
    scan_local <<<BATCH*NCHUNK*DIM/256, 256>>>(k, v, decay, 0);
    scan_prefix<<<BATCH*DIM/256,        256>>>(decay);
    scan_local <<<BATCH*NCHUNK*DIM/256, 256>>>(k, v, decay, 1);

    // chain + all three GEMMs fused, overlapped via chunk flags
    mega_kernel<<<NCHAIN + NWORK, 256>>>(q, A, gw, gb, Bm, ow, ob, out);
}